// round 1
// baseline (speedup 1.0000x reference)
#include <cuda_runtime.h>
#include <mma.h>
#include <math_constants.h>
#include <cstdint>
#include <cstddef>

using namespace nvcuda;

// Problem constants (fixed shapes for this problem)
static const int kB  = 8;
static const int kS  = 4096;
static const int kH  = 16;
static const int kHD = 64;
static const int kD  = 1024;      // H*HD
static const int kM  = kB * kS;   // 32768 rows
static const int kW  = 16;        // one-sided window

// Scratch (device globals: allocation-free per harness rules)
__device__ float g_qkv[(size_t)kM * 3 * kD];   // [M][3072]  h-major: h*192 + {q:0..63,k:64..127,v:128..191}
__device__ float g_attn[(size_t)kM * kD];      // [M][1024]  attention output, col = h*64+d

// ---------------------------------------------------------------------------
// TF32 WMMA GEMM:  C[M,N] = A[M,K] @ B[K,N] + bias[N]
// Block tile 128x128, K-step 16, 8 warps (2x4), warp tile 64x32 = 4x2 frags.
// mode==0: A = Aext (x), C = g_qkv   (QKV projection)
// mode==1: A = g_attn,   C = Cext    (output projection -> d_out)
// ---------------------------------------------------------------------------
#define BM 128
#define BN 128
#define BK 16
#define LDA 20    // 16 + 4 pad (multiple of 4 for wmma ldm, rows 16B aligned)
#define LDB 132   // 128 + 4 pad
#define LDST 20

__global__ __launch_bounds__(256, 2)
void gemm_tf32(const float* __restrict__ Aext, const float* __restrict__ Bw,
               const float* __restrict__ bias, float* __restrict__ Cext,
               int M, int N, int K, int mode)
{
    __shared__ __align__(16) float As[2][BM][LDA];
    __shared__ __align__(16) float Bs[2][BK][LDB];
    __shared__ __align__(16) float St[8][16][LDST];

    const float* A = (mode == 0) ? Aext : g_attn;
    float*       C = (mode == 0) ? g_qkv : Cext;

    const int tid    = threadIdx.x;
    const int warpId = tid >> 5;
    const int lane   = tid & 31;
    const int warpM  = warpId & 1;    // 0..1  -> 64-row slice
    const int warpN  = warpId >> 1;   // 0..3  -> 32-col slice
    const int m0 = blockIdx.y * BM;
    const int n0 = blockIdx.x * BN;

    wmma::fragment<wmma::accumulator, 16, 16, 8, float> cf[4][2];
#pragma unroll
    for (int i = 0; i < 4; i++)
#pragma unroll
        for (int j = 0; j < 2; j++)
            wmma::fill_fragment(cf[i][j], 0.0f);

    // Cooperative-load indexing (256 threads)
    const int ar0 = tid >> 2;           // 0..63   (A rows, 2 per thread)
    const int ac  = (tid & 3) * 4;      // 0,4,8,12
    const int br0 = tid >> 5;           // 0..7    (B rows, 2 per thread)
    const int bc  = (tid & 31) * 4;     // 0..124

    // ---- preload tile 0 ----
    {
#pragma unroll
        for (int i = 0; i < 2; i++) {
            int r = ar0 + i * 64;
            float4 v = *(const float4*)(A + (size_t)(m0 + r) * K + ac);
            As[0][r][ac + 0] = wmma::__float_to_tf32(v.x);
            As[0][r][ac + 1] = wmma::__float_to_tf32(v.y);
            As[0][r][ac + 2] = wmma::__float_to_tf32(v.z);
            As[0][r][ac + 3] = wmma::__float_to_tf32(v.w);
        }
#pragma unroll
        for (int i = 0; i < 2; i++) {
            int r = br0 + i * 8;
            float4 v = *(const float4*)(Bw + (size_t)r * N + n0 + bc);
            Bs[0][r][bc + 0] = wmma::__float_to_tf32(v.x);
            Bs[0][r][bc + 1] = wmma::__float_to_tf32(v.y);
            Bs[0][r][bc + 2] = wmma::__float_to_tf32(v.z);
            Bs[0][r][bc + 3] = wmma::__float_to_tf32(v.w);
        }
    }
    __syncthreads();

    const int nT = K / BK;
    for (int t = 0; t < nT; t++) {
        const int buf = t & 1;
        float4 pa0, pa1, pb0, pb1;
        const bool next = (t + 1 < nT);
        if (next) {
            const int k0 = (t + 1) * BK;
            pa0 = *(const float4*)(A + (size_t)(m0 + ar0)      * K + k0 + ac);
            pa1 = *(const float4*)(A + (size_t)(m0 + ar0 + 64) * K + k0 + ac);
            pb0 = *(const float4*)(Bw + (size_t)(k0 + br0)     * N + n0 + bc);
            pb1 = *(const float4*)(Bw + (size_t)(k0 + br0 + 8) * N + n0 + bc);
        }
#pragma unroll
        for (int kk = 0; kk < 2; kk++) {
            wmma::fragment<wmma::matrix_a, 16, 16, 8, wmma::precision::tf32, wmma::row_major> af[4];
            wmma::fragment<wmma::matrix_b, 16, 16, 8, wmma::precision::tf32, wmma::row_major> bf[2];
#pragma unroll
            for (int i = 0; i < 4; i++)
                wmma::load_matrix_sync(af[i], &As[buf][warpM * 64 + i * 16][kk * 8], LDA);
#pragma unroll
            for (int j = 0; j < 2; j++)
                wmma::load_matrix_sync(bf[j], &Bs[buf][kk * 8][warpN * 32 + j * 16], LDB);
#pragma unroll
            for (int i = 0; i < 4; i++)
#pragma unroll
                for (int j = 0; j < 2; j++)
                    wmma::mma_sync(cf[i][j], af[i], bf[j], cf[i][j]);
        }
        if (next) {
            const int nb = buf ^ 1;
            As[nb][ar0][ac + 0] = wmma::__float_to_tf32(pa0.x);
            As[nb][ar0][ac + 1] = wmma::__float_to_tf32(pa0.y);
            As[nb][ar0][ac + 2] = wmma::__float_to_tf32(pa0.z);
            As[nb][ar0][ac + 3] = wmma::__float_to_tf32(pa0.w);
            As[nb][ar0 + 64][ac + 0] = wmma::__float_to_tf32(pa1.x);
            As[nb][ar0 + 64][ac + 1] = wmma::__float_to_tf32(pa1.y);
            As[nb][ar0 + 64][ac + 2] = wmma::__float_to_tf32(pa1.z);
            As[nb][ar0 + 64][ac + 3] = wmma::__float_to_tf32(pa1.w);
            Bs[nb][br0][bc + 0] = wmma::__float_to_tf32(pb0.x);
            Bs[nb][br0][bc + 1] = wmma::__float_to_tf32(pb0.y);
            Bs[nb][br0][bc + 2] = wmma::__float_to_tf32(pb0.z);
            Bs[nb][br0][bc + 3] = wmma::__float_to_tf32(pb0.w);
            Bs[nb][br0 + 8][bc + 0] = wmma::__float_to_tf32(pb1.x);
            Bs[nb][br0 + 8][bc + 1] = wmma::__float_to_tf32(pb1.y);
            Bs[nb][br0 + 8][bc + 2] = wmma::__float_to_tf32(pb1.z);
            Bs[nb][br0 + 8][bc + 3] = wmma::__float_to_tf32(pb1.w);
        }
        __syncthreads();
    }

    // ---- epilogue: frag -> per-warp smem stage -> bias add -> coalesced f4 stores ----
#pragma unroll
    for (int i = 0; i < 4; i++) {
#pragma unroll
        for (int j = 0; j < 2; j++) {
            wmma::store_matrix_sync(&St[warpId][0][0], cf[i][j], LDST, wmma::mem_row_major);
            __syncwarp();
            const int mb = m0 + warpM * 64 + i * 16;
            const int nb = n0 + warpN * 32 + j * 16;
#pragma unroll
            for (int p = 0; p < 2; p++) {
                int e  = lane + p * 32;   // 0..63
                int r  = e >> 2;          // 0..15
                int c4 = (e & 3) * 4;     // 0,4,8,12
                float4 v;
                v.x = St[warpId][r][c4 + 0] + bias[nb + c4 + 0];
                v.y = St[warpId][r][c4 + 1] + bias[nb + c4 + 1];
                v.z = St[warpId][r][c4 + 2] + bias[nb + c4 + 2];
                v.w = St[warpId][r][c4 + 3] + bias[nb + c4 + 3];
                *(float4*)(C + (size_t)(mb + r) * N + nb + c4) = v;
            }
            __syncwarp();
        }
    }
}

// ---------------------------------------------------------------------------
// Sliding-window attention, exact fp32.
// Grid (S/64, H, B), 64 threads: thread t owns query s0+t.
// K tile (96 rows x 64) staged in smem (pad 65 -> conflict-free), then reused
// for V after a sync. Window = 33 offsets; OOB keys -> -inf logits.
// ---------------------------------------------------------------------------
__global__ __launch_bounds__(64)
void attn_swin(const float* __restrict__ bqkv)
{
    __shared__ float kv[96][65];
    const int b  = blockIdx.z;
    const int h  = blockIdx.y;
    const int s0 = blockIdx.x * 64;
    const int tid = threadIdx.x;
    const int s   = s0 + tid;

    // ---- stage K rows [s0-16, s0+80) ----
    const int colK = h * 192 + 64;
    for (int i = tid; i < 96 * 16; i += 64) {
        int r = i >> 4, c4 = (i & 15) * 4;
        int key = s0 - kW + r;
        float4 v = make_float4(0.f, 0.f, 0.f, 0.f);
        if (key >= 0 && key < kS) {
            v = *(const float4*)(g_qkv + (size_t)(b * kS + key) * 3072 + colK + c4);
            float4 bb = *(const float4*)(bqkv + colK + c4);
            v.x += bb.x; v.y += bb.y; v.z += bb.z; v.w += bb.w;
        }
        kv[r][c4 + 0] = v.x; kv[r][c4 + 1] = v.y; kv[r][c4 + 2] = v.z; kv[r][c4 + 3] = v.w;
    }

    // ---- q into registers ----
    float q[64];
    {
        const int colQ = h * 192;
        const float* qp = g_qkv + (size_t)(b * kS + s) * 3072 + colQ;
#pragma unroll
        for (int c4 = 0; c4 < 64; c4 += 4) {
            float4 v  = *(const float4*)(qp + c4);
            float4 bb = *(const float4*)(bqkv + colQ + c4);
            q[c4 + 0] = v.x + bb.x; q[c4 + 1] = v.y + bb.y;
            q[c4 + 2] = v.z + bb.z; q[c4 + 3] = v.w + bb.w;
        }
    }
    __syncthreads();

    // ---- banded logits + softmax ----
    float lg[33];
#pragma unroll
    for (int o = 0; o < 33; o++) {
        int key = s + o - kW;
        if (key >= 0 && key < kS) {
            float acc = 0.f;
#pragma unroll
            for (int d = 0; d < 64; d++) acc += q[d] * kv[tid + o][d];
            lg[o] = acc * 0.125f;   // 1/sqrt(64)
        } else {
            lg[o] = -CUDART_INF_F;
        }
    }
    float mx = lg[0];
#pragma unroll
    for (int o = 1; o < 33; o++) mx = fmaxf(mx, lg[o]);
    float sum = 0.f;
#pragma unroll
    for (int o = 0; o < 33; o++) {
        float p = (lg[o] == -CUDART_INF_F) ? 0.f : __expf(lg[o] - mx);
        lg[o] = p;
        sum += p;
    }
    const float inv = 1.0f / sum;
#pragma unroll
    for (int o = 0; o < 33; o++) lg[o] *= inv;

    __syncthreads();   // everyone done reading K tile

    // ---- stage V rows over the same smem ----
    const int colV = h * 192 + 128;
    for (int i = tid; i < 96 * 16; i += 64) {
        int r = i >> 4, c4 = (i & 15) * 4;
        int key = s0 - kW + r;
        float4 v = make_float4(0.f, 0.f, 0.f, 0.f);
        if (key >= 0 && key < kS) {
            v = *(const float4*)(g_qkv + (size_t)(b * kS + key) * 3072 + colV + c4);
            float4 bb = *(const float4*)(bqkv + colV + c4);
            v.x += bb.x; v.y += bb.y; v.z += bb.z; v.w += bb.w;
        }
        kv[r][c4 + 0] = v.x; kv[r][c4 + 1] = v.y; kv[r][c4 + 2] = v.z; kv[r][c4 + 3] = v.w;
    }
    __syncthreads();

    // ---- probs @ V ----
    float acc[64];
#pragma unroll
    for (int d = 0; d < 64; d++) acc[d] = 0.f;
#pragma unroll
    for (int o = 0; o < 33; o++) {
        float p = lg[o];
#pragma unroll
        for (int d = 0; d < 64; d++) acc[d] += p * kv[tid + o][d];
    }

    float* op = g_attn + (size_t)(b * kS + s) * kD + h * kHD;
#pragma unroll
    for (int c4 = 0; c4 < 64; c4 += 4) {
        float4 v = make_float4(acc[c4], acc[c4 + 1], acc[c4 + 2], acc[c4 + 3]);
        *(float4*)(op + c4) = v;
    }
}

// ---------------------------------------------------------------------------
extern "C" void kernel_launch(void* const* d_in, const int* in_sizes, int n_in,
                              void* d_out, int out_size)
{
    const float* x    = (const float*)d_in[0];
    const float* Wqkv = (const float*)d_in[1];
    const float* bqkv = (const float*)d_in[2];
    const float* Wo   = (const float*)d_in[3];
    const float* bo   = (const float*)d_in[4];
    float* out = (float*)d_out;

    // 1) QKV projection: g_qkv = x @ Wqkv + bqkv      [32768, 3072]
    {
        dim3 grid(3 * kD / BN, kM / BM);   // (24, 256)
        gemm_tf32<<<grid, 256>>>(x, Wqkv, bqkv, nullptr, kM, 3 * kD, kD, 0);
    }

    // 2) Sliding-window attention: g_attn [32768, 1024]
    {
        dim3 grid(kS / 64, kH, kB);        // (64, 16, 8)
        attn_swin<<<grid, 64>>>(bqkv);
    }

    // 3) Output projection: out = g_attn @ Wo + bo    [32768, 1024]
    {
        dim3 grid(kD / BN, kM / BM);       // (8, 256)
        gemm_tf32<<<grid, 256>>>(nullptr, Wo, bo, out, kM, kD, kD, 1);
    }
}

// round 6
// speedup vs baseline: 3.2156x; 3.2156x over previous
#include <cuda_runtime.h>
#include <cuda_fp16.h>
#include <mma.h>
#include <math_constants.h>
#include <cstdint>
#include <cstddef>

using namespace nvcuda;

// Problem constants
#define KB 8
#define KS 4096
#define KH 16
#define KD 1024
#define KM 32768      // B*S
#define KW 16

// Device scratch (allocation-free rules)
__device__ __align__(256) float  g_qkv  [(size_t)KM * 3072];  // fp32 QKV (+bias), col = h*192 + {q,k,v}
__device__ __align__(256) __half g_xh   [(size_t)KM * KD];    // x in fp16
__device__ __align__(256) __half g_attnh[(size_t)KM * KD];    // attention out in fp16
__device__ __align__(256) __half g_wqkvh[1024 * 3072];        // Wqkv fp16 [K][N]
__device__ __align__(256) __half g_woh  [1024 * 1024];        // Wo   fp16 [K][N]

// ---------------------------------------------------------------------------
// cp.async helpers
// ---------------------------------------------------------------------------
__device__ __forceinline__ uint32_t smem_u32(const void* p) {
    return (uint32_t)__cvta_generic_to_shared((void*)p);
}
__device__ __forceinline__ void cp_async16(uint32_t dst, const void* src) {
    asm volatile("cp.async.cg.shared.global [%0], [%1], 16;\n" :: "r"(dst), "l"(src) : "memory");
}
__device__ __forceinline__ void cp_commit() { asm volatile("cp.async.commit_group;\n" ::: "memory"); }
__device__ __forceinline__ void cp_wait1()  { asm volatile("cp.async.wait_group 1;\n" ::: "memory"); }
__device__ __forceinline__ void cp_wait0()  { asm volatile("cp.async.wait_group 0;\n" ::: "memory"); }

// ---------------------------------------------------------------------------
// fp32 -> fp16 convert (vectorized, grid-stride). n must be a multiple of 4.
// ---------------------------------------------------------------------------
__global__ void f2h(const float* __restrict__ in, __half* __restrict__ out, int n)
{
    int i = (blockIdx.x * blockDim.x + threadIdx.x) * 4;
    const int stride = gridDim.x * blockDim.x * 4;
    for (; i < n; i += stride) {
        float4 v = *(const float4*)(in + i);
        __half2 h0 = __floats2half2_rn(v.x, v.y);
        __half2 h1 = __floats2half2_rn(v.z, v.w);
        uint2 u;
        u.x = *reinterpret_cast<uint32_t*>(&h0);
        u.y = *reinterpret_cast<uint32_t*>(&h1);
        *(uint2*)(out + i) = u;
    }
}

// ---------------------------------------------------------------------------
// fp16 WMMA GEMM:  C[M,N](fp32) = A[M,K](fp16) @ B[K,N](fp16) + bias[N]
// Block tile 128x128, BK=32, 8 warps (2x4), warp tile 64x32 (4x2 frags of
// 16x16x16). cp.async double-buffered stage fills; ldmatrix fragment loads.
// Epilogue: bias loaded once as replicated accumulator fragment, direct
// global store_matrix_sync.
// ---------------------------------------------------------------------------
#define GBK 32
#define LDA 40     // 32 + 8 pad (halves)
#define LDB 136    // 128 + 8 pad (halves)

__global__ __launch_bounds__(256, 2)
void gemm_fp16(const __half* __restrict__ A, const __half* __restrict__ Bw,
               const float* __restrict__ bias, float* __restrict__ C,
               int N, int K)
{
    __shared__ __align__(16) __half As[2][128][LDA];
    __shared__ __align__(16) __half Bs[2][GBK][LDB];
    __shared__ __align__(16) float  bsm[16][LDB];

    const int tid    = threadIdx.x;
    const int warpId = tid >> 5;
    const int warpM  = warpId & 1;    // 0..1 -> 64-row slice
    const int warpN  = warpId >> 1;   // 0..3 -> 32-col slice
    const int m0 = blockIdx.y * 128;
    const int n0 = blockIdx.x * 128;
    const int nT = K / GBK;

    // bias -> smem, replicated over 16 rows (for accumulator-fragment load)
    for (int i = tid; i < 16 * 128; i += 256) {
        int r = i >> 7, c = i & 127;
        bsm[r][c] = bias[n0 + c];
    }

    wmma::fragment<wmma::accumulator, 16, 16, 16, float> cf[4][2];
#pragma unroll
    for (int i = 0; i < 4; i++)
#pragma unroll
        for (int j = 0; j < 2; j++)
            wmma::fill_fragment(cf[i][j], 0.0f);

    // fill lambda-ish macro work: 1024 16B chunks per stage (A 512 + B 512)
    auto fill = [&](int t, int buf) {
        const int k0 = t * GBK;
        // A tile: 128 rows x 32 halves (4 chunks/row)
#pragma unroll
        for (int u = 0; u < 2; u++) {
            int idx = tid + u * 256;           // 0..511
            int r   = idx >> 2;
            int cc  = (idx & 3) * 8;           // half offset
            uint32_t dst = smem_u32(&As[buf][r][cc]);
            cp_async16(dst, A + (size_t)(m0 + r) * K + k0 + cc);
        }
        // B tile: 32 rows x 128 halves (16 chunks/row)
#pragma unroll
        for (int u = 0; u < 2; u++) {
            int idx = tid + u * 256;
            int r   = idx >> 4;
            int cc  = (idx & 15) * 8;
            uint32_t dst = smem_u32(&Bs[buf][r][cc]);
            cp_async16(dst, Bw + (size_t)(k0 + r) * N + n0 + cc);
        }
    };

    // prologue
    fill(0, 0);
    cp_commit();

    for (int t = 0; t < nT; t++) {
        const int buf  = t & 1;
        const bool nxt = (t + 1 < nT);
        if (nxt) { fill(t + 1, buf ^ 1); cp_commit(); cp_wait1(); }
        else     { cp_wait0(); }
        __syncthreads();

#pragma unroll
        for (int kk = 0; kk < 2; kk++) {
            wmma::fragment<wmma::matrix_a, 16, 16, 16, __half, wmma::row_major> af[4];
            wmma::fragment<wmma::matrix_b, 16, 16, 16, __half, wmma::row_major> bf[2];
#pragma unroll
            for (int i = 0; i < 4; i++)
                wmma::load_matrix_sync(af[i], &As[buf][warpM * 64 + i * 16][kk * 16], LDA);
#pragma unroll
            for (int j = 0; j < 2; j++)
                wmma::load_matrix_sync(bf[j], &Bs[buf][kk * 16][warpN * 32 + j * 16], LDB);
#pragma unroll
            for (int i = 0; i < 4; i++)
#pragma unroll
                for (int j = 0; j < 2; j++)
                    wmma::mma_sync(cf[i][j], af[i], bf[j], cf[i][j]);
        }
        __syncthreads();   // protect buf before next iteration's fill overwrites it
    }

    // epilogue: += bias fragment, direct global store
    wmma::fragment<wmma::accumulator, 16, 16, 16, float> bfr[2];
#pragma unroll
    for (int j = 0; j < 2; j++)
        wmma::load_matrix_sync(bfr[j], &bsm[0][warpN * 32 + j * 16], LDB, wmma::mem_row_major);

#pragma unroll
    for (int i = 0; i < 4; i++) {
#pragma unroll
        for (int j = 0; j < 2; j++) {
#pragma unroll
            for (int e = 0; e < cf[i][j].num_elements; e++)
                cf[i][j].x[e] += bfr[j].x[e];
            float* cp_ = C + (size_t)(m0 + warpM * 64 + i * 16) * N + n0 + warpN * 32 + j * 16;
            wmma::store_matrix_sync(cp_, cf[i][j], N, wmma::mem_row_major);
        }
    }
}

// ---------------------------------------------------------------------------
// Sliding-window attention, exact fp32. 128 queries per block, 128 threads.
// K/V tile 160 rows x 64 staged in smem (stride 65, conflict-free).
// Reads fp32 g_qkv (bias already applied by GEMM1); writes fp16 g_attnh.
// ---------------------------------------------------------------------------
__global__ __launch_bounds__(128)
void attn_swin()
{
    __shared__ float kv[160][65];
    const int b  = blockIdx.z;
    const int h  = blockIdx.y;
    const int s0 = blockIdx.x * 128;
    const int tid = threadIdx.x;
    const int s   = s0 + tid;

    // ---- stage K rows [s0-16, s0+144) ----
    const int colK = h * 192 + 64;
    for (int i = tid; i < 160 * 16; i += 128) {
        int r = i >> 4, c4 = (i & 15) * 4;
        int key = s0 - KW + r;
        float4 v = make_float4(0.f, 0.f, 0.f, 0.f);
        if (key >= 0 && key < KS)
            v = *(const float4*)(g_qkv + (size_t)(b * KS + key) * 3072 + colK + c4);
        kv[r][c4 + 0] = v.x; kv[r][c4 + 1] = v.y; kv[r][c4 + 2] = v.z; kv[r][c4 + 3] = v.w;
    }

    // ---- q into registers ----
    float q[64];
    {
        const float* qp = g_qkv + (size_t)(b * KS + s) * 3072 + h * 192;
#pragma unroll
        for (int c4 = 0; c4 < 64; c4 += 4) {
            float4 v = *(const float4*)(qp + c4);
            q[c4 + 0] = v.x; q[c4 + 1] = v.y; q[c4 + 2] = v.z; q[c4 + 3] = v.w;
        }
    }
    __syncthreads();

    // ---- banded logits + softmax ----
    float lg[33];
#pragma unroll
    for (int o = 0; o < 33; o++) {
        int key = s + o - KW;
        if (key >= 0 && key < KS) {
            float acc = 0.f;
#pragma unroll
            for (int d = 0; d < 64; d++) acc += q[d] * kv[tid + o][d];
            lg[o] = acc * 0.125f;   // 1/sqrt(64)
        } else {
            lg[o] = -CUDART_INF_F;
        }
    }
    float mx = lg[0];
#pragma unroll
    for (int o = 1; o < 33; o++) mx = fmaxf(mx, lg[o]);
    float sum = 0.f;
#pragma unroll
    for (int o = 0; o < 33; o++) {
        float p = (lg[o] == -CUDART_INF_F) ? 0.f : __expf(lg[o] - mx);
        lg[o] = p;
        sum += p;
    }
    const float inv = 1.0f / sum;
#pragma unroll
    for (int o = 0; o < 33; o++) lg[o] *= inv;

    __syncthreads();   // all done reading K tile

    // ---- stage V rows over the same smem ----
    const int colV = h * 192 + 128;
    for (int i = tid; i < 160 * 16; i += 128) {
        int r = i >> 4, c4 = (i & 15) * 4;
        int key = s0 - KW + r;
        float4 v = make_float4(0.f, 0.f, 0.f, 0.f);
        if (key >= 0 && key < KS)
            v = *(const float4*)(g_qkv + (size_t)(b * KS + key) * 3072 + colV + c4);
        kv[r][c4 + 0] = v.x; kv[r][c4 + 1] = v.y; kv[r][c4 + 2] = v.z; kv[r][c4 + 3] = v.w;
    }
    __syncthreads();

    // ---- probs @ V ----
    float acc[64];
#pragma unroll
    for (int d = 0; d < 64; d++) acc[d] = 0.f;
#pragma unroll
    for (int o = 0; o < 33; o++) {
        float p = lg[o];
#pragma unroll
        for (int d = 0; d < 64; d++) acc[d] += p * kv[tid + o][d];
    }

    // ---- write fp16 output (16B packed stores) ----
    __half* op = g_attnh + (size_t)(b * KS + s) * KD + h * 64;
#pragma unroll
    for (int c = 0; c < 64; c += 8) {
        __half2 h0 = __floats2half2_rn(acc[c + 0], acc[c + 1]);
        __half2 h1 = __floats2half2_rn(acc[c + 2], acc[c + 3]);
        __half2 h2 = __floats2half2_rn(acc[c + 4], acc[c + 5]);
        __half2 h3 = __floats2half2_rn(acc[c + 6], acc[c + 7]);
        uint4 u;
        u.x = *reinterpret_cast<uint32_t*>(&h0);
        u.y = *reinterpret_cast<uint32_t*>(&h1);
        u.z = *reinterpret_cast<uint32_t*>(&h2);
        u.w = *reinterpret_cast<uint32_t*>(&h3);
        *(uint4*)(op + c) = u;
    }
}

// ---------------------------------------------------------------------------
extern "C" void kernel_launch(void* const* d_in, const int* in_sizes, int n_in,
                              void* d_out, int out_size)
{
    const float* x    = (const float*)d_in[0];
    const float* Wqkv = (const float*)d_in[1];
    const float* bqkv = (const float*)d_in[2];
    const float* Wo   = (const float*)d_in[3];
    const float* bo   = (const float*)d_in[4];
    float* out = (float*)d_out;

    void *p_qkv, *p_xh, *p_attnh, *p_wqkvh, *p_woh;
    cudaGetSymbolAddress(&p_qkv,   g_qkv);
    cudaGetSymbolAddress(&p_xh,    g_xh);
    cudaGetSymbolAddress(&p_attnh, g_attnh);
    cudaGetSymbolAddress(&p_wqkvh, g_wqkvh);
    cudaGetSymbolAddress(&p_woh,   g_woh);

    // 0) fp32 -> fp16 converts (x, Wqkv, Wo)
    f2h<<<4096, 256>>>(x,    (__half*)p_xh,    KM * KD);
    f2h<<<1024, 256>>>(Wqkv, (__half*)p_wqkvh, 1024 * 3072);
    f2h<<<512,  256>>>(Wo,   (__half*)p_woh,   1024 * 1024);

    // 1) QKV projection: g_qkv = x @ Wqkv + bqkv   [32768, 3072] fp32 out
    gemm_fp16<<<dim3(3072 / 128, KM / 128), 256>>>(
        (const __half*)p_xh, (const __half*)p_wqkvh, bqkv, (float*)p_qkv, 3072, 1024);

    // 2) Sliding-window attention -> g_attnh [32768, 1024] fp16
    attn_swin<<<dim3(KS / 128, KH, KB), 128>>>();

    // 3) Output projection: out = g_attnh @ Wo + bo  [32768, 1024]
    gemm_fp16<<<dim3(1024 / 128, KM / 128), 256>>>(
        (const __half*)p_attnh, (const __half*)p_woh, bo, out, 1024, 1024);
}

// round 8
// speedup vs baseline: 3.2615x; 1.0143x over previous
#include <cuda_runtime.h>
#include <cuda_fp16.h>
#include <mma.h>
#include <math_constants.h>
#include <cstdint>
#include <cstddef>

using namespace nvcuda;

// Problem constants
#define KB 8
#define KS 4096
#define KH 16
#define KD 1024
#define KM 32768      // B*S
#define KW 16

// Device scratch (allocation-free rules)
__device__ __align__(256) __half g_qkvh [(size_t)KM * 3072];  // fp16 QKV (+bias), col = h*192 + {q,k,v}
__device__ __align__(256) __half g_xh   [(size_t)KM * KD];    // x in fp16
__device__ __align__(256) __half g_attnh[(size_t)KM * KD];    // attention out fp16
__device__ __align__(256) __half g_wqkvh[1024 * 3072];        // Wqkv fp16 [K][N]
__device__ __align__(256) __half g_woh  [1024 * 1024];        // Wo   fp16 [K][N]

// ---------------------------------------------------------------------------
// cp.async helpers
// ---------------------------------------------------------------------------
__device__ __forceinline__ uint32_t smem_u32(const void* p) {
    return (uint32_t)__cvta_generic_to_shared((void*)p);
}
__device__ __forceinline__ void cp_async16(uint32_t dst, const void* src) {
    asm volatile("cp.async.cg.shared.global [%0], [%1], 16;\n" :: "r"(dst), "l"(src) : "memory");
}
__device__ __forceinline__ void cp_commit() { asm volatile("cp.async.commit_group;\n" ::: "memory"); }
__device__ __forceinline__ void cp_wait2()  { asm volatile("cp.async.wait_group 2;\n" ::: "memory"); }

// ---------------------------------------------------------------------------
// fp32 -> fp16 convert
// ---------------------------------------------------------------------------
__global__ void f2h(const float* __restrict__ in, __half* __restrict__ out, int n)
{
    int i = (blockIdx.x * blockDim.x + threadIdx.x) * 4;
    const int stride = gridDim.x * blockDim.x * 4;
    for (; i < n; i += stride) {
        float4 v = *(const float4*)(in + i);
        __half2 h0 = __floats2half2_rn(v.x, v.y);
        __half2 h1 = __floats2half2_rn(v.z, v.w);
        uint2 u;
        u.x = *reinterpret_cast<uint32_t*>(&h0);
        u.y = *reinterpret_cast<uint32_t*>(&h1);
        *(uint2*)(out + i) = u;
    }
}

// ---------------------------------------------------------------------------
// fp16 WMMA GEMM: C[M,N] = A[M,K]h @ B[K,N]h + bias[N]
// CTA tile 128x256, BK=32, 8 warps (2x4), warp tile 64x64 (4x4 frags).
// 4-stage cp.async ring, one __syncthreads per K-chunk.
// Bias pre-loaded into accumulator fragments. HALF_OUT: C fp16 else fp32.
// ---------------------------------------------------------------------------
#define ST_BYTES 27136           // A: 128*80B=10240, B: 32*528B=16896
#define AB_OFF   10240
#define BIAS_OFF (4 * ST_BYTES)  // 108544
#define GEMM_SMEM (BIAS_OFF + 16 * 264 * 4)   // 125440

template<bool HALF_OUT>
__global__ __launch_bounds__(256, 1)
void gemm_big(const __half* __restrict__ A, const __half* __restrict__ Bw,
              const float* __restrict__ bias, void* __restrict__ Cv,
              int N, int K)
{
    extern __shared__ __align__(16) char sm[];
    const uint32_t sbase = smem_u32(sm);
    const int tid    = threadIdx.x;
    const int warpId = tid >> 5;
    const int lane   = tid & 31;
    const int warpM  = warpId & 1;    // 0..1 -> 64 rows
    const int warpN  = warpId >> 1;   // 0..3 -> 64 cols
    const int m0 = blockIdx.y * 128;
    const int n0 = blockIdx.x * 256;
    const int nT = K >> 5;            // 32

    // bias -> smem replicated over 16 rows (ldm 264)
    float* bsm = (float*)(sm + BIAS_OFF);
    for (int i = tid; i < 16 * 256; i += 256)
        bsm[(i >> 8) * 264 + (i & 255)] = bias[n0 + (i & 255)];

    auto fill = [&](int t, int slot) {
        const int k0 = t << 5;
        const uint32_t sb = sbase + (uint32_t)slot * ST_BYTES;
#pragma unroll
        for (int u = 0; u < 2; u++) {
            int i = tid + u * 256;          // 0..511
            int r = i >> 2, c = (i & 3) * 8;
            cp_async16(sb + r * 80 + c * 2, A + (size_t)(m0 + r) * K + k0 + c);
        }
#pragma unroll
        for (int u = 0; u < 4; u++) {
            int i = tid + u * 256;          // 0..1023
            int r = i >> 5, c = (i & 31) * 8;
            cp_async16(sb + AB_OFF + r * 528 + c * 2, Bw + (size_t)(k0 + r) * N + n0 + c);
        }
    };

    fill(0, 0); cp_commit();
    fill(1, 1); cp_commit();
    fill(2, 2); cp_commit();

    __syncthreads();   // bias smem visible
    wmma::fragment<wmma::accumulator, 16, 16, 16, float> cf[4][4];
    {
        wmma::fragment<wmma::accumulator, 16, 16, 16, float> bfr;
#pragma unroll
        for (int j = 0; j < 4; j++) {
            wmma::load_matrix_sync(bfr, &bsm[warpN * 64 + j * 16], 264, wmma::mem_row_major);
#pragma unroll
            for (int i = 0; i < 4; i++)
#pragma unroll
                for (int e = 0; e < bfr.num_elements; e++)
                    cf[i][j].x[e] = bfr.x[e];
        }
    }

    for (int t = 0; t < nT; t++) {
        const int slot = t & 3;
        cp_wait2();
        __syncthreads();
        if (t + 3 < nT) { fill(t + 3, (t + 3) & 3); cp_commit(); }

        const __half* As_ = (const __half*)(sm + (size_t)slot * ST_BYTES);
        const __half* Bs_ = (const __half*)(sm + (size_t)slot * ST_BYTES + AB_OFF);
#pragma unroll
        for (int kk = 0; kk < 2; kk++) {
            wmma::fragment<wmma::matrix_b, 16, 16, 16, __half, wmma::row_major> bf[4];
#pragma unroll
            for (int j = 0; j < 4; j++)
                wmma::load_matrix_sync(bf[j], &Bs_[(kk * 16) * 264 + warpN * 64 + j * 16], 264);
#pragma unroll
            for (int i = 0; i < 4; i++) {
                wmma::fragment<wmma::matrix_a, 16, 16, 16, __half, wmma::row_major> af;
                wmma::load_matrix_sync(af, &As_[(warpM * 64 + i * 16) * 40 + kk * 16], 40);
#pragma unroll
                for (int j = 0; j < 4; j++)
                    wmma::mma_sync(cf[i][j], af, bf[j], cf[i][j]);
            }
        }
    }

    __syncthreads();   // free smem for staging

    if (HALF_OUT) {
        float* stg = (float*)sm + warpId * 320;    // 16x20 per warp
        __half* C = (__half*)Cv;
#pragma unroll
        for (int i = 0; i < 4; i++) {
#pragma unroll
            for (int j = 0; j < 4; j++) {
                wmma::store_matrix_sync(stg, cf[i][j], 20, wmma::mem_row_major);
                __syncwarp();
                int r  = lane >> 1;
                int c8 = (lane & 1) * 8;
                const float* s = stg + r * 20 + c8;
                __half2 h0 = __floats2half2_rn(s[0], s[1]);
                __half2 h1 = __floats2half2_rn(s[2], s[3]);
                __half2 h2 = __floats2half2_rn(s[4], s[5]);
                __half2 h3 = __floats2half2_rn(s[6], s[7]);
                uint4 u;
                u.x = *reinterpret_cast<uint32_t*>(&h0);
                u.y = *reinterpret_cast<uint32_t*>(&h1);
                u.z = *reinterpret_cast<uint32_t*>(&h2);
                u.w = *reinterpret_cast<uint32_t*>(&h3);
                *(uint4*)(C + (size_t)(m0 + warpM * 64 + i * 16 + r) * N
                              + n0 + warpN * 64 + j * 16 + c8) = u;
                __syncwarp();
            }
        }
    } else {
        float* C = (float*)Cv;
#pragma unroll
        for (int i = 0; i < 4; i++)
#pragma unroll
            for (int j = 0; j < 4; j++)
                wmma::store_matrix_sync(C + (size_t)(m0 + warpM * 64 + i * 16) * N
                                          + n0 + warpN * 64 + j * 16,
                                        cf[i][j], N, wmma::mem_row_major);
    }
}

// ---------------------------------------------------------------------------
// WMMA sliding-window attention (chunked-dense).
// Block = 64 queries x one (b,h). Keys s0-16 .. s0+79 (96 rows).
// S = Q@K^T via WMMA (fp32 acc) -> masked softmax in smem -> P fp16 -> P@V.
// 128 threads (4 warps); warp w owns query rows 16w..16w+15.
// ---------------------------------------------------------------------------
#define AQ_OFF 0                 // Qs 64x72 half  = 9216
#define AK_OFF 9216              // Ks 96x72 half  = 13824
#define AV_OFF 23040             // Vs 96x72 half  = 13824
#define AS_OFF 36864             // Sf 64x100 float= 25600
#define AP_OFF 62464             // Ps 64x104 half = 13312
#define ATT_SMEM 75776

__global__ __launch_bounds__(128)
void attn_wmma()
{
    extern __shared__ __align__(16) char sm[];
    __half* Qh = (__half*)(sm + AQ_OFF);
    __half* Kh = (__half*)(sm + AK_OFF);
    __half* Vh = (__half*)(sm + AV_OFF);
    float*  Sf = (float*)(sm + AS_OFF);
    __half* Ph = (__half*)(sm + AP_OFF);

    const int b  = blockIdx.z;
    const int h  = blockIdx.y;
    const int s0 = blockIdx.x * 64;
    const int tid  = threadIdx.x;
    const int w    = tid >> 5;
    const int lane = tid & 31;

    // ---- load Q (64x64), K,V (96x64) fp16 tiles ----
    const __half* qbase = g_qkvh + (size_t)(b * KS) * 3072 + h * 192;
    for (int i = tid; i < 512; i += 128) {
        int r = i >> 3, c = (i & 7) * 8;
        *(uint4*)(Qh + r * 72 + c) = *(const uint4*)(qbase + (size_t)(s0 + r) * 3072 + c);
    }
    for (int i = tid; i < 768; i += 128) {
        int r = i >> 3, c = (i & 7) * 8;
        int key = s0 - KW + r;
        key = key < 0 ? 0 : (key >= KS ? KS - 1 : key);   // clamp; masked later
        *(uint4*)(Kh + r * 72 + c) = *(const uint4*)(qbase + (size_t)key * 3072 + 64 + c);
    }
    for (int i = tid; i < 768; i += 128) {
        int r = i >> 3, c = (i & 7) * 8;
        int key = s0 - KW + r;
        key = key < 0 ? 0 : (key >= KS ? KS - 1 : key);
        *(uint4*)(Vh + r * 72 + c) = *(const uint4*)(qbase + (size_t)key * 3072 + 128 + c);
    }
    __syncthreads();

    // ---- S = Q @ K^T  (warp w: rows 16w..16w+15, all 96 cols) ----
    {
        wmma::fragment<wmma::matrix_a, 16, 16, 16, __half, wmma::row_major> af[4];
#pragma unroll
        for (int k = 0; k < 4; k++)
            wmma::load_matrix_sync(af[k], &Qh[(w * 16) * 72 + k * 16], 72);
#pragma unroll
        for (int n = 0; n < 6; n++) {
            wmma::fragment<wmma::accumulator, 16, 16, 16, float> sc;
            wmma::fill_fragment(sc, 0.0f);
#pragma unroll
            for (int k = 0; k < 4; k++) {
                wmma::fragment<wmma::matrix_b, 16, 16, 16, __half, wmma::col_major> bf;
                wmma::load_matrix_sync(bf, &Kh[(n * 16) * 72 + k * 16], 72);
                wmma::mma_sync(sc, af[k], bf, sc);
            }
            wmma::store_matrix_sync(&Sf[(w * 16) * 100 + n * 16], sc, 100, wmma::mem_row_major);
        }
    }
    __syncthreads();

    // ---- masked softmax: 2 threads per row (48 cols each) ----
    {
        const int row  = tid >> 1;
        const int hlf  = tid & 1;
        int jlo = row;                 // window: key >= t-16  <=> j >= row
        if (s0 - KW + jlo < 0) jlo = KW - s0;
        int jhi = row + 32;            // window: key <= t+16
        const int jmax = KS - 1 - s0 + KW;
        if (jhi > jmax) jhi = jmax;
        const int ja = hlf * 48;
        const int lo = jlo > ja ? jlo : ja;
        const int hi = jhi < ja + 47 ? jhi : ja + 47;

        float* Srow = Sf + row * 100;
        float m = -1e30f;
        for (int j = lo; j <= hi; j++) m = fmaxf(m, Srow[j]);
        m = fmaxf(m, __shfl_xor_sync(0xffffffffu, m, 1));
        float s = 0.f;
        for (int j = lo; j <= hi; j++) {
            float e = __expf(0.125f * (Srow[j] - m));
            Srow[j] = e;
            s += e;
        }
        s += __shfl_xor_sync(0xffffffffu, s, 1);
        const float inv = 1.0f / s;
        __half* Prow = Ph + row * 104;
        for (int j = ja; j < ja + 48; j++) {
            float p = (j >= lo && j <= hi) ? Srow[j] * inv : 0.f;
            Prow[j] = __float2half(p);
        }
    }
    __syncthreads();

    // ---- O = P @ V  (warp w: rows 16w..16w+15, 64 cols) ----
    {
        wmma::fragment<wmma::accumulator, 16, 16, 16, float> of[4];
#pragma unroll
        for (int n = 0; n < 4; n++) wmma::fill_fragment(of[n], 0.0f);
#pragma unroll
        for (int k = 0; k < 6; k++) {
            wmma::fragment<wmma::matrix_a, 16, 16, 16, __half, wmma::row_major> af;
            wmma::load_matrix_sync(af, &Ph[(w * 16) * 104 + k * 16], 104);
#pragma unroll
            for (int n = 0; n < 4; n++) {
                wmma::fragment<wmma::matrix_b, 16, 16, 16, __half, wmma::row_major> bf;
                wmma::load_matrix_sync(bf, &Vh[(k * 16) * 72 + n * 16], 72);
                wmma::mma_sync(of[n], af, bf, of[n]);
            }
        }
        // write fp16 output via per-warp staging (reuse Q region)
        float* stg = (float*)sm + w * 320;   // 16x20
#pragma unroll
        for (int n = 0; n < 4; n++) {
            wmma::store_matrix_sync(stg, of[n], 20, wmma::mem_row_major);
            __syncwarp();
            int r  = lane >> 1;
            int c8 = (lane & 1) * 8;
            const float* sp = stg + r * 20 + c8;
            __half2 h0 = __floats2half2_rn(sp[0], sp[1]);
            __half2 h1 = __floats2half2_rn(sp[2], sp[3]);
            __half2 h2 = __floats2half2_rn(sp[4], sp[5]);
            __half2 h3 = __floats2half2_rn(sp[6], sp[7]);
            uint4 u;
            u.x = *reinterpret_cast<uint32_t*>(&h0);
            u.y = *reinterpret_cast<uint32_t*>(&h1);
            u.z = *reinterpret_cast<uint32_t*>(&h2);
            u.w = *reinterpret_cast<uint32_t*>(&h3);
            *(uint4*)(g_attnh + (size_t)(b * KS + s0 + w * 16 + r) * KD
                               + h * 64 + n * 16 + c8) = u;
            __syncwarp();
        }
    }
}

// ---------------------------------------------------------------------------
extern "C" void kernel_launch(void* const* d_in, const int* in_sizes, int n_in,
                              void* d_out, int out_size)
{
    const float* x    = (const float*)d_in[0];
    const float* Wqkv = (const float*)d_in[1];
    const float* bqkv = (const float*)d_in[2];
    const float* Wo   = (const float*)d_in[3];
    const float* bo   = (const float*)d_in[4];
    float* out = (float*)d_out;

    void *p_qkvh, *p_xh, *p_attnh, *p_wqkvh, *p_woh;
    cudaGetSymbolAddress(&p_qkvh,  g_qkvh);
    cudaGetSymbolAddress(&p_xh,    g_xh);
    cudaGetSymbolAddress(&p_attnh, g_attnh);
    cudaGetSymbolAddress(&p_wqkvh, g_wqkvh);
    cudaGetSymbolAddress(&p_woh,   g_woh);

    cudaFuncSetAttribute(gemm_big<true>,  cudaFuncAttributeMaxDynamicSharedMemorySize, GEMM_SMEM);
    cudaFuncSetAttribute(gemm_big<false>, cudaFuncAttributeMaxDynamicSharedMemorySize, GEMM_SMEM);
    cudaFuncSetAttribute(attn_wmma, cudaFuncAttributeMaxDynamicSharedMemorySize, ATT_SMEM);

    // 0) fp32 -> fp16 converts
    f2h<<<4096, 256>>>(x,    (__half*)p_xh,    KM * KD);
    f2h<<<1024, 256>>>(Wqkv, (__half*)p_wqkvh, 1024 * 3072);
    f2h<<<512,  256>>>(Wo,   (__half*)p_woh,   1024 * 1024);

    // 1) QKV projection (fp16 out): g_qkvh = x @ Wqkv + bqkv
    gemm_big<true><<<dim3(3072 / 256, KM / 128), 256, GEMM_SMEM>>>(
        (const __half*)p_xh, (const __half*)p_wqkvh, bqkv, p_qkvh, 3072, 1024);

    // 2) WMMA sliding-window attention -> g_attnh
    attn_wmma<<<dim3(KS / 64, KH, KB), 128, ATT_SMEM>>>();

    // 3) Output projection (fp32 out): out = g_attnh @ Wo + bo
    gemm_big<false><<<dim3(1024 / 256, KM / 128), 256, GEMM_SMEM>>>(
        (const __half*)p_attnh, (const __half*)p_woh, bo, out, 1024, 1024);
}

// round 9
// speedup vs baseline: 3.5625x; 1.0923x over previous
#include <cuda_runtime.h>
#include <cuda_fp16.h>
#include <mma.h>
#include <math_constants.h>
#include <cstdint>
#include <cstddef>

using namespace nvcuda;

// Problem constants
#define KB 8
#define KS 4096
#define KH 16
#define KD 1024
#define KM 32768      // B*S
#define KW 16

// Device scratch (allocation-free rules)
__device__ __align__(256) __half g_qkvh [(size_t)KM * 3072];  // fp16 QKV (+bias)
__device__ __align__(256) __half g_xh   [(size_t)KM * KD];    // x in fp16
__device__ __align__(256) __half g_attnh[(size_t)KM * KD];    // attention out fp16
__device__ __align__(256) __half g_wqkvh[1024 * 3072];        // Wqkv fp16 [K][N]
__device__ __align__(256) __half g_woh  [1024 * 1024];        // Wo   fp16 [K][N]

// ---------------------------------------------------------------------------
// cp.async helpers
// ---------------------------------------------------------------------------
__device__ __forceinline__ uint32_t smem_u32(const void* p) {
    return (uint32_t)__cvta_generic_to_shared((void*)p);
}
__device__ __forceinline__ void cp_async16(uint32_t dst, const void* src) {
    asm volatile("cp.async.cg.shared.global [%0], [%1], 16;\n" :: "r"(dst), "l"(src) : "memory");
}
__device__ __forceinline__ void cp_commit() { asm volatile("cp.async.commit_group;\n" ::: "memory"); }
__device__ __forceinline__ void cp_wait0()  { asm volatile("cp.async.wait_group 0;\n" ::: "memory"); }
__device__ __forceinline__ void cp_wait1()  { asm volatile("cp.async.wait_group 1;\n" ::: "memory"); }
__device__ __forceinline__ void cp_wait2()  { asm volatile("cp.async.wait_group 2;\n" ::: "memory"); }

// ---------------------------------------------------------------------------
// fp32 -> fp16 convert
// ---------------------------------------------------------------------------
__global__ void f2h(const float* __restrict__ in, __half* __restrict__ out, int n)
{
    int i = (blockIdx.x * blockDim.x + threadIdx.x) * 4;
    const int stride = gridDim.x * blockDim.x * 4;
    for (; i < n; i += stride) {
        float4 v = *(const float4*)(in + i);
        __half2 h0 = __floats2half2_rn(v.x, v.y);
        __half2 h1 = __floats2half2_rn(v.z, v.w);
        uint2 u;
        u.x = *reinterpret_cast<uint32_t*>(&h0);
        u.y = *reinterpret_cast<uint32_t*>(&h1);
        *(uint2*)(out + i) = u;
    }
}

// ---------------------------------------------------------------------------
// fp16 WMMA GEMM: C[M,N] = A[M,K]h @ B[K,N]h + bias[N]
// CTA tile 128x128, BK=32, 8 warps (2x4), warp tile 64x32 (4x2 frags).
// 4-stage cp.async ring, 3-deep prefetch, ONE __syncthreads per K-iter.
// Bias preloaded into accumulator fragments. 2 CTAs/SM.
// ---------------------------------------------------------------------------
#define G_LDA 40                     // A row stride (halves): 32 + 8
#define G_LDB 136                    // B row stride (halves): 128 + 8
#define G_STG (128 * G_LDA * 2 + 32 * G_LDB * 2)   // 10240 + 8704 = 18944
#define G_BOFF  (4 * G_STG)          // 75776
#define G_SMEM  (G_BOFF + 16 * G_LDB * 4)          // 84480

template<bool HALF_OUT>
__global__ __launch_bounds__(256, 2)
void gemm_p4(const __half* __restrict__ A, const __half* __restrict__ Bw,
             const float* __restrict__ bias, void* __restrict__ Cv,
             int N, int K)
{
    extern __shared__ __align__(16) char sm[];
    const uint32_t sbase = smem_u32(sm);
    const int tid    = threadIdx.x;
    const int warpId = tid >> 5;
    const int lane   = tid & 31;
    const int warpM  = warpId & 1;    // 0..1 -> 64 rows
    const int warpN  = warpId >> 1;   // 0..3 -> 32 cols
    const int m0 = blockIdx.y * 128;
    const int n0 = blockIdx.x * 128;
    const int nT = K >> 5;

    // bias -> smem, replicated over 16 rows
    float* bsm = (float*)(sm + G_BOFF);
    for (int i = tid; i < 16 * 128; i += 256)
        bsm[(i >> 7) * G_LDB + (i & 127)] = bias[n0 + (i & 127)];

    auto fill = [&](int t, int slot) {
        const int k0 = t << 5;
        const uint32_t sb = sbase + (uint32_t)slot * G_STG;
        // A: 128 rows x 32 halves = 512 chunks
#pragma unroll
        for (int u = 0; u < 2; u++) {
            int i = tid + u * 256;
            int r = i >> 2, c = (i & 3) * 8;
            cp_async16(sb + r * (G_LDA * 2) + c * 2, A + (size_t)(m0 + r) * K + k0 + c);
        }
        // B: 32 rows x 128 halves = 512 chunks
#pragma unroll
        for (int u = 0; u < 2; u++) {
            int i = tid + u * 256;
            int r = i >> 4, c = (i & 15) * 8;
            cp_async16(sb + 128 * (G_LDA * 2) + r * (G_LDB * 2) + c * 2,
                       Bw + (size_t)(k0 + r) * N + n0 + c);
        }
    };

    fill(0, 0); cp_commit();
    fill(1, 1); cp_commit();
    fill(2, 2); cp_commit();

    __syncthreads();   // bias visible
    wmma::fragment<wmma::accumulator, 16, 16, 16, float> cf[4][2];
    {
        wmma::fragment<wmma::accumulator, 16, 16, 16, float> bfr;
#pragma unroll
        for (int j = 0; j < 2; j++) {
            wmma::load_matrix_sync(bfr, &bsm[warpN * 32 + j * 16], G_LDB, wmma::mem_row_major);
#pragma unroll
            for (int i = 0; i < 4; i++)
#pragma unroll
                for (int e = 0; e < bfr.num_elements; e++)
                    cf[i][j].x[e] = bfr.x[e];
        }
    }

    for (int t = 0; t < nT; t++) {
        const int slot = t & 3;
        if      (t + 2 < nT) cp_wait2();
        else if (t + 1 < nT) cp_wait1();
        else                 cp_wait0();
        __syncthreads();
        // prefetch stage t+3 into the slot compute(t-1) vacated (safe: the sync
        // above means every warp finished reading it)
        if (t + 3 < nT) { fill(t + 3, (t + 3) & 3); cp_commit(); }

        const __half* As_ = (const __half*)(sm + (size_t)slot * G_STG);
        const __half* Bs_ = (const __half*)(sm + (size_t)slot * G_STG + 128 * G_LDA * 2);
#pragma unroll
        for (int kk = 0; kk < 2; kk++) {
            wmma::fragment<wmma::matrix_b, 16, 16, 16, __half, wmma::row_major> bf[2];
#pragma unroll
            for (int j = 0; j < 2; j++)
                wmma::load_matrix_sync(bf[j], &Bs_[(kk * 16) * G_LDB + warpN * 32 + j * 16], G_LDB);
#pragma unroll
            for (int i = 0; i < 4; i++) {
                wmma::fragment<wmma::matrix_a, 16, 16, 16, __half, wmma::row_major> af;
                wmma::load_matrix_sync(af, &As_[(warpM * 64 + i * 16) * G_LDA + kk * 16], G_LDA);
#pragma unroll
                for (int j = 0; j < 2; j++)
                    wmma::mma_sync(cf[i][j], af, bf[j], cf[i][j]);
            }
        }
    }

    __syncthreads();   // free smem for epilogue staging

    if (HALF_OUT) {
        float* stg = (float*)sm + warpId * 320;   // 16x20 per warp
        __half* C = (__half*)Cv;
#pragma unroll
        for (int i = 0; i < 4; i++) {
#pragma unroll
            for (int j = 0; j < 2; j++) {
                wmma::store_matrix_sync(stg, cf[i][j], 20, wmma::mem_row_major);
                __syncwarp();
                int r  = lane >> 1;
                int c8 = (lane & 1) * 8;
                const float* s = stg + r * 20 + c8;
                __half2 h0 = __floats2half2_rn(s[0], s[1]);
                __half2 h1 = __floats2half2_rn(s[2], s[3]);
                __half2 h2 = __floats2half2_rn(s[4], s[5]);
                __half2 h3 = __floats2half2_rn(s[6], s[7]);
                uint4 u;
                u.x = *reinterpret_cast<uint32_t*>(&h0);
                u.y = *reinterpret_cast<uint32_t*>(&h1);
                u.z = *reinterpret_cast<uint32_t*>(&h2);
                u.w = *reinterpret_cast<uint32_t*>(&h3);
                *(uint4*)(C + (size_t)(m0 + warpM * 64 + i * 16 + r) * N
                              + n0 + warpN * 32 + j * 16 + c8) = u;
                __syncwarp();
            }
        }
    } else {
        float* C = (float*)Cv;
#pragma unroll
        for (int i = 0; i < 4; i++)
#pragma unroll
            for (int j = 0; j < 2; j++)
                wmma::store_matrix_sync(C + (size_t)(m0 + warpM * 64 + i * 16) * N
                                          + n0 + warpN * 32 + j * 16,
                                        cf[i][j], N, wmma::mem_row_major);
    }
}

// ---------------------------------------------------------------------------
// WMMA sliding-window attention (chunked-dense) — unchanged from round 8.
// Block = 64 queries x one (b,h). Keys s0-16 .. s0+79 (96 rows).
// ---------------------------------------------------------------------------
#define AQ_OFF 0                 // Qs 64x72 half  = 9216
#define AK_OFF 9216              // Ks 96x72 half  = 13824
#define AV_OFF 23040             // Vs 96x72 half  = 13824
#define AS_OFF 36864             // Sf 64x100 float= 25600
#define AP_OFF 62464             // Ps 64x104 half = 13312
#define ATT_SMEM 75776

__global__ __launch_bounds__(128)
void attn_wmma()
{
    extern __shared__ __align__(16) char sm[];
    __half* Qh = (__half*)(sm + AQ_OFF);
    __half* Kh = (__half*)(sm + AK_OFF);
    __half* Vh = (__half*)(sm + AV_OFF);
    float*  Sf = (float*)(sm + AS_OFF);
    __half* Ph = (__half*)(sm + AP_OFF);

    const int b  = blockIdx.z;
    const int h  = blockIdx.y;
    const int s0 = blockIdx.x * 64;
    const int tid  = threadIdx.x;
    const int w    = tid >> 5;
    const int lane = tid & 31;

    const __half* qbase = g_qkvh + (size_t)(b * KS) * 3072 + h * 192;
    for (int i = tid; i < 512; i += 128) {
        int r = i >> 3, c = (i & 7) * 8;
        *(uint4*)(Qh + r * 72 + c) = *(const uint4*)(qbase + (size_t)(s0 + r) * 3072 + c);
    }
    for (int i = tid; i < 768; i += 128) {
        int r = i >> 3, c = (i & 7) * 8;
        int key = s0 - KW + r;
        key = key < 0 ? 0 : (key >= KS ? KS - 1 : key);
        *(uint4*)(Kh + r * 72 + c) = *(const uint4*)(qbase + (size_t)key * 3072 + 64 + c);
    }
    for (int i = tid; i < 768; i += 128) {
        int r = i >> 3, c = (i & 7) * 8;
        int key = s0 - KW + r;
        key = key < 0 ? 0 : (key >= KS ? KS - 1 : key);
        *(uint4*)(Vh + r * 72 + c) = *(const uint4*)(qbase + (size_t)key * 3072 + 128 + c);
    }
    __syncthreads();

    // S = Q @ K^T
    {
        wmma::fragment<wmma::matrix_a, 16, 16, 16, __half, wmma::row_major> af[4];
#pragma unroll
        for (int k = 0; k < 4; k++)
            wmma::load_matrix_sync(af[k], &Qh[(w * 16) * 72 + k * 16], 72);
#pragma unroll
        for (int n = 0; n < 6; n++) {
            wmma::fragment<wmma::accumulator, 16, 16, 16, float> sc;
            wmma::fill_fragment(sc, 0.0f);
#pragma unroll
            for (int k = 0; k < 4; k++) {
                wmma::fragment<wmma::matrix_b, 16, 16, 16, __half, wmma::col_major> bf;
                wmma::load_matrix_sync(bf, &Kh[(n * 16) * 72 + k * 16], 72);
                wmma::mma_sync(sc, af[k], bf, sc);
            }
            wmma::store_matrix_sync(&Sf[(w * 16) * 100 + n * 16], sc, 100, wmma::mem_row_major);
        }
    }
    __syncthreads();

    // masked softmax: 2 threads per row
    {
        const int row  = tid >> 1;
        const int hlf  = tid & 1;
        int jlo = row;
        if (s0 - KW + jlo < 0) jlo = KW - s0;
        int jhi = row + 32;
        const int jmax = KS - 1 - s0 + KW;
        if (jhi > jmax) jhi = jmax;
        const int ja = hlf * 48;
        const int lo = jlo > ja ? jlo : ja;
        const int hi = jhi < ja + 47 ? jhi : ja + 47;

        float* Srow = Sf + row * 100;
        float m = -1e30f;
        for (int j = lo; j <= hi; j++) m = fmaxf(m, Srow[j]);
        m = fmaxf(m, __shfl_xor_sync(0xffffffffu, m, 1));
        float s = 0.f;
        for (int j = lo; j <= hi; j++) {
            float e = __expf(0.125f * (Srow[j] - m));
            Srow[j] = e;
            s += e;
        }
        s += __shfl_xor_sync(0xffffffffu, s, 1);
        const float inv = 1.0f / s;
        __half* Prow = Ph + row * 104;
        for (int j = ja; j < ja + 48; j++) {
            float p = (j >= lo && j <= hi) ? Srow[j] * inv : 0.f;
            Prow[j] = __float2half(p);
        }
    }
    __syncthreads();

    // O = P @ V
    {
        wmma::fragment<wmma::accumulator, 16, 16, 16, float> of[4];
#pragma unroll
        for (int n = 0; n < 4; n++) wmma::fill_fragment(of[n], 0.0f);
#pragma unroll
        for (int k = 0; k < 6; k++) {
            wmma::fragment<wmma::matrix_a, 16, 16, 16, __half, wmma::row_major> af;
            wmma::load_matrix_sync(af, &Ph[(w * 16) * 104 + k * 16], 104);
#pragma unroll
            for (int n = 0; n < 4; n++) {
                wmma::fragment<wmma::matrix_b, 16, 16, 16, __half, wmma::row_major> bf;
                wmma::load_matrix_sync(bf, &Vh[(k * 16) * 72 + n * 16], 72);
                wmma::mma_sync(of[n], af, bf, of[n]);
            }
        }
        float* stg = (float*)sm + w * 320;
#pragma unroll
        for (int n = 0; n < 4; n++) {
            wmma::store_matrix_sync(stg, of[n], 20, wmma::mem_row_major);
            __syncwarp();
            int r  = lane >> 1;
            int c8 = (lane & 1) * 8;
            const float* sp = stg + r * 20 + c8;
            __half2 h0 = __floats2half2_rn(sp[0], sp[1]);
            __half2 h1 = __floats2half2_rn(sp[2], sp[3]);
            __half2 h2 = __floats2half2_rn(sp[4], sp[5]);
            __half2 h3 = __floats2half2_rn(sp[6], sp[7]);
            uint4 u;
            u.x = *reinterpret_cast<uint32_t*>(&h0);
            u.y = *reinterpret_cast<uint32_t*>(&h1);
            u.z = *reinterpret_cast<uint32_t*>(&h2);
            u.w = *reinterpret_cast<uint32_t*>(&h3);
            *(uint4*)(g_attnh + (size_t)(b * KS + s0 + w * 16 + r) * KD
                               + h * 64 + n * 16 + c8) = u;
            __syncwarp();
        }
    }
}

// ---------------------------------------------------------------------------
extern "C" void kernel_launch(void* const* d_in, const int* in_sizes, int n_in,
                              void* d_out, int out_size)
{
    const float* x    = (const float*)d_in[0];
    const float* Wqkv = (const float*)d_in[1];
    const float* bqkv = (const float*)d_in[2];
    const float* Wo   = (const float*)d_in[3];
    const float* bo   = (const float*)d_in[4];
    float* out = (float*)d_out;

    void *p_qkvh, *p_xh, *p_attnh, *p_wqkvh, *p_woh;
    cudaGetSymbolAddress(&p_qkvh,  g_qkvh);
    cudaGetSymbolAddress(&p_xh,    g_xh);
    cudaGetSymbolAddress(&p_attnh, g_attnh);
    cudaGetSymbolAddress(&p_wqkvh, g_wqkvh);
    cudaGetSymbolAddress(&p_woh,   g_woh);

    cudaFuncSetAttribute(gemm_p4<true>,  cudaFuncAttributeMaxDynamicSharedMemorySize, G_SMEM);
    cudaFuncSetAttribute(gemm_p4<false>, cudaFuncAttributeMaxDynamicSharedMemorySize, G_SMEM);
    cudaFuncSetAttribute(attn_wmma, cudaFuncAttributeMaxDynamicSharedMemorySize, ATT_SMEM);

    // 0) fp32 -> fp16 converts
    f2h<<<4096, 256>>>(x,    (__half*)p_xh,    KM * KD);
    f2h<<<1024, 256>>>(Wqkv, (__half*)p_wqkvh, 1024 * 3072);
    f2h<<<512,  256>>>(Wo,   (__half*)p_woh,   1024 * 1024);

    // 1) QKV projection (fp16 out): g_qkvh = x @ Wqkv + bqkv
    gemm_p4<true><<<dim3(3072 / 128, KM / 128), 256, G_SMEM>>>(
        (const __half*)p_xh, (const __half*)p_wqkvh, bqkv, p_qkvh, 3072, 1024);

    // 2) WMMA sliding-window attention -> g_attnh
    attn_wmma<<<dim3(KS / 64, KH, KB), 128, ATT_SMEM>>>();

    // 3) Output projection (fp32 out): out = g_attnh @ Wo + bo
    gemm_p4<false><<<dim3(1024 / 128, KM / 128), 256, G_SMEM>>>(
        (const __half*)p_attnh, (const __half*)p_woh, bo, out, 1024, 1024);
}

// round 11
// speedup vs baseline: 4.0045x; 1.1241x over previous
#include <cuda_runtime.h>
#include <cuda_fp16.h>
#include <mma.h>
#include <math_constants.h>
#include <cstdint>
#include <cstddef>

using namespace nvcuda;

// Problem constants
#define KB 8
#define KS 4096
#define KH 16
#define KD 1024
#define KM 32768      // B*S
#define KW 16

// Device scratch (allocation-free rules)
__device__ __align__(256) __half g_qkvh [(size_t)KM * 3072];  // fp16 QKV (+bias)
__device__ __align__(256) __half g_xh   [(size_t)KM * KD];    // x in fp16
__device__ __align__(256) __half g_attnh[(size_t)KM * KD];    // attention out fp16
__device__ __align__(256) __half g_wqkvh[1024 * 3072];        // Wqkv fp16 [K][N]
__device__ __align__(256) __half g_woh  [1024 * 1024];        // Wo   fp16 [K][N]

// ---------------------------------------------------------------------------
// cp.async helpers
// ---------------------------------------------------------------------------
__device__ __forceinline__ uint32_t smem_u32(const void* p) {
    return (uint32_t)__cvta_generic_to_shared((void*)p);
}
__device__ __forceinline__ void cp_async16(uint32_t dst, const void* src) {
    asm volatile("cp.async.cg.shared.global [%0], [%1], 16;\n" :: "r"(dst), "l"(src) : "memory");
}
__device__ __forceinline__ void cp_commit() { asm volatile("cp.async.commit_group;\n" ::: "memory"); }
__device__ __forceinline__ void cp_wait0()  { asm volatile("cp.async.wait_group 0;\n" ::: "memory"); }
__device__ __forceinline__ void cp_wait1()  { asm volatile("cp.async.wait_group 1;\n" ::: "memory"); }

// ---------------------------------------------------------------------------
// fp32 -> fp16 convert
// ---------------------------------------------------------------------------
__global__ void f2h(const float* __restrict__ in, __half* __restrict__ out, int n)
{
    int i = (blockIdx.x * blockDim.x + threadIdx.x) * 4;
    const int stride = gridDim.x * blockDim.x * 4;
    for (; i < n; i += stride) {
        float4 v = *(const float4*)(in + i);
        __half2 h0 = __floats2half2_rn(v.x, v.y);
        __half2 h1 = __floats2half2_rn(v.z, v.w);
        uint2 u;
        u.x = *reinterpret_cast<uint32_t*>(&h0);
        u.y = *reinterpret_cast<uint32_t*>(&h1);
        *(uint2*)(out + i) = u;
    }
}

// ---------------------------------------------------------------------------
// fp16 WMMA GEMM: C[M,N] = A[M,K]h @ B[K,N]h + bias[N]
// CTA tile 128x128, BK=64 (16 iters), 8 warps (2x4), warp tile 64x32.
// 3-stage cp.async ring, 2-deep prefetch, ONE __syncthreads per K-iter.
// Bias added in epilogue from gmem (L1-cached). 2 CTAs/SM.
// ---------------------------------------------------------------------------
#define G_LDA 72                     // A row stride (halves): 64 + 8  (144B, conflict-free)
#define G_LDB 136                    // B row stride (halves): 128 + 8 (272B, conflict-free)
#define G_ASZ (128 * G_LDA * 2)      // 18432
#define G_STG (G_ASZ + 64 * G_LDB * 2)   // 18432 + 17408 = 35840
#define G_SMEM (3 * G_STG)           // 107520

template<bool HALF_OUT>
__global__ __launch_bounds__(256, 2)
void gemm_k64(const __half* __restrict__ A, const __half* __restrict__ Bw,
              const float* __restrict__ bias, void* __restrict__ Cv,
              int N, int K)
{
    extern __shared__ __align__(16) char sm[];
    const uint32_t sbase = smem_u32(sm);
    const int tid    = threadIdx.x;
    const int warpId = tid >> 5;
    const int lane   = tid & 31;
    const int warpM  = warpId & 1;    // 0..1 -> 64 rows
    const int warpN  = warpId >> 1;   // 0..3 -> 32 cols
    const int m0 = blockIdx.y * 128;
    const int n0 = blockIdx.x * 128;
    const int nT = K >> 6;            // 16

    auto fill = [&](int t, int slot) {
        const int k0 = t << 6;
        const uint32_t sb = sbase + (uint32_t)slot * G_STG;
        // A: 128 rows x 64 halves = 1024 chunks (8/row)
#pragma unroll
        for (int u = 0; u < 4; u++) {
            int i = tid + u * 256;
            int r = i >> 3, c = (i & 7) * 8;
            cp_async16(sb + r * (G_LDA * 2) + c * 2, A + (size_t)(m0 + r) * K + k0 + c);
        }
        // B: 64 rows x 128 halves = 1024 chunks (16/row)
#pragma unroll
        for (int u = 0; u < 4; u++) {
            int i = tid + u * 256;
            int r = i >> 4, c = (i & 15) * 8;
            cp_async16(sb + G_ASZ + r * (G_LDB * 2) + c * 2,
                       Bw + (size_t)(k0 + r) * N + n0 + c);
        }
    };

    fill(0, 0); cp_commit();
    fill(1, 1); cp_commit();

    wmma::fragment<wmma::accumulator, 16, 16, 16, float> cf[4][2];
#pragma unroll
    for (int i = 0; i < 4; i++)
#pragma unroll
        for (int j = 0; j < 2; j++)
            wmma::fill_fragment(cf[i][j], 0.0f);

    for (int t = 0; t < nT; t++) {
        const int slot = t % 3;
        if (t + 1 < nT) cp_wait1(); else cp_wait0();
        __syncthreads();
        // prefetch t+2 into the slot compute(t-1) vacated (protected by sync)
        if (t + 2 < nT) { fill(t + 2, (t + 2) % 3); cp_commit(); }

        const __half* As_ = (const __half*)(sm + (size_t)slot * G_STG);
        const __half* Bs_ = (const __half*)(sm + (size_t)slot * G_STG + G_ASZ);
#pragma unroll
        for (int kk = 0; kk < 4; kk++) {
            wmma::fragment<wmma::matrix_b, 16, 16, 16, __half, wmma::row_major> bf[2];
#pragma unroll
            for (int j = 0; j < 2; j++)
                wmma::load_matrix_sync(bf[j], &Bs_[(kk * 16) * G_LDB + warpN * 32 + j * 16], G_LDB);
#pragma unroll
            for (int i = 0; i < 4; i++) {
                wmma::fragment<wmma::matrix_a, 16, 16, 16, __half, wmma::row_major> af;
                wmma::load_matrix_sync(af, &As_[(warpM * 64 + i * 16) * G_LDA + kk * 16], G_LDA);
#pragma unroll
                for (int j = 0; j < 2; j++)
                    wmma::mma_sync(cf[i][j], af, bf[j], cf[i][j]);
            }
        }
    }

    __syncthreads();   // stage smem dead -> reuse for epilogue staging

    float* stg = (float*)sm + warpId * 320;   // 16x20 per warp
    const int r  = lane >> 1;
    const int c8 = (lane & 1) * 8;
#pragma unroll
    for (int j = 0; j < 2; j++) {
        const float* bp = bias + n0 + warpN * 32 + j * 16 + c8;
        const float4 b0 = *(const float4*)bp;
        const float4 b1 = *(const float4*)(bp + 4);
#pragma unroll
        for (int i = 0; i < 4; i++) {
            wmma::store_matrix_sync(stg, cf[i][j], 20, wmma::mem_row_major);
            __syncwarp();
            const float* s = stg + r * 20 + c8;
            float v0 = s[0] + b0.x, v1 = s[1] + b0.y, v2 = s[2] + b0.z, v3 = s[3] + b0.w;
            float v4 = s[4] + b1.x, v5 = s[5] + b1.y, v6 = s[6] + b1.z, v7 = s[7] + b1.w;
            const size_t row = (size_t)(m0 + warpM * 64 + i * 16 + r);
            const int    col = n0 + warpN * 32 + j * 16 + c8;
            if (HALF_OUT) {
                __half2 h0 = __floats2half2_rn(v0, v1);
                __half2 h1 = __floats2half2_rn(v2, v3);
                __half2 h2 = __floats2half2_rn(v4, v5);
                __half2 h3 = __floats2half2_rn(v6, v7);
                uint4 u;
                u.x = *reinterpret_cast<uint32_t*>(&h0);
                u.y = *reinterpret_cast<uint32_t*>(&h1);
                u.z = *reinterpret_cast<uint32_t*>(&h2);
                u.w = *reinterpret_cast<uint32_t*>(&h3);
                *(uint4*)((__half*)Cv + row * N + col) = u;
            } else {
                *(float4*)((float*)Cv + row * N + col)     = make_float4(v0, v1, v2, v3);
                *(float4*)((float*)Cv + row * N + col + 4) = make_float4(v4, v5, v6, v7);
            }
            __syncwarp();
        }
    }
}

// ---------------------------------------------------------------------------
// WMMA sliding-window attention, 256 threads (8 warps) per 64-query block.
// Keys s0-16 .. s0+79 (96 rows). QK and PV each split across all 8 warps.
// P (fp16) overlays the dead K region; epilogue staging overlays Sf.
// ---------------------------------------------------------------------------
#define AQ_OFF 0                 // Qs 64x72 half  = 9216
#define AK_OFF 9216              // Ks 96x72 half  = 13824 ; later Ph 64x104 half (13312)
#define AV_OFF 23040             // Vs 96x72 half  = 13824
#define AS_OFF 36864             // Sf 64x100 float= 25600 ; later stg 8x320 float
#define ATT_SMEM 62464

__global__ __launch_bounds__(256)
void attn_wmma()
{
    extern __shared__ __align__(16) char sm[];
    __half* Qh = (__half*)(sm + AQ_OFF);
    __half* Kh = (__half*)(sm + AK_OFF);
    __half* Vh = (__half*)(sm + AV_OFF);
    float*  Sf = (float*)(sm + AS_OFF);
    __half* Ph = (__half*)(sm + AK_OFF);   // overlays K (dead after QK)

    const int b  = blockIdx.z;
    const int h  = blockIdx.y;
    const int s0 = blockIdx.x * 64;
    const int tid  = threadIdx.x;
    const int w    = tid >> 5;

    // ---- load Q (64x64), K,V (96x64) fp16 tiles ----
    const __half* qbase = g_qkvh + (size_t)(b * KS) * 3072 + h * 192;
#pragma unroll
    for (int u = 0; u < 2; u++) {
        int i = tid + u * 256;
        int r = i >> 3, c = (i & 7) * 8;
        *(uint4*)(Qh + r * 72 + c) = *(const uint4*)(qbase + (size_t)(s0 + r) * 3072 + c);
    }
#pragma unroll
    for (int u = 0; u < 3; u++) {
        int i = tid + u * 256;
        int r = i >> 3, c = (i & 7) * 8;
        int key = s0 - KW + r;
        key = key < 0 ? 0 : (key >= KS ? KS - 1 : key);
        *(uint4*)(Kh + r * 72 + c) = *(const uint4*)(qbase + (size_t)key * 3072 + 64 + c);
    }
#pragma unroll
    for (int u = 0; u < 3; u++) {
        int i = tid + u * 256;
        int r = i >> 3, c = (i & 7) * 8;
        int key = s0 - KW + r;
        key = key < 0 ? 0 : (key >= KS ? KS - 1 : key);
        *(uint4*)(Vh + r * 72 + c) = *(const uint4*)(qbase + (size_t)key * 3072 + 128 + c);
    }
    __syncthreads();

    // ---- S = Q @ K^T : warp w -> rows 16*(w&3), n-tiles (w>>2)*3 .. +2 ----
    {
        const int wr = (w & 3) * 16;
        const int nb = (w >> 2) * 3;
        wmma::fragment<wmma::matrix_a, 16, 16, 16, __half, wmma::row_major> af[4];
#pragma unroll
        for (int k = 0; k < 4; k++)
            wmma::load_matrix_sync(af[k], &Qh[wr * 72 + k * 16], 72);
#pragma unroll
        for (int nn = 0; nn < 3; nn++) {
            const int n = nb + nn;
            wmma::fragment<wmma::accumulator, 16, 16, 16, float> sc;
            wmma::fill_fragment(sc, 0.0f);
#pragma unroll
            for (int k = 0; k < 4; k++) {
                wmma::fragment<wmma::matrix_b, 16, 16, 16, __half, wmma::col_major> bf;
                wmma::load_matrix_sync(bf, &Kh[(n * 16) * 72 + k * 16], 72);
                wmma::mma_sync(sc, af[k], bf, sc);
            }
            wmma::store_matrix_sync(&Sf[wr * 100 + n * 16], sc, 100, wmma::mem_row_major);
        }
    }
    __syncthreads();

    // ---- masked softmax: 4 threads per row (24 cols each) ----
    {
        const int row = tid >> 2;
        const int sub = tid & 3;
        int jlo = row;
        if (s0 - KW + jlo < 0) jlo = KW - s0;
        int jhi = row + 32;
        const int jmax = KS - 1 - s0 + KW;
        if (jhi > jmax) jhi = jmax;
        const int ja = sub * 24;
        const int lo = jlo > ja ? jlo : ja;
        const int hi = jhi < ja + 23 ? jhi : ja + 23;

        float* Srow = Sf + row * 100;
        float m = -1e30f;
        for (int j = lo; j <= hi; j++) m = fmaxf(m, Srow[j]);
        m = fmaxf(m, __shfl_xor_sync(0xffffffffu, m, 1));
        m = fmaxf(m, __shfl_xor_sync(0xffffffffu, m, 2));
        float s = 0.f;
        for (int j = lo; j <= hi; j++) {
            float e = __expf(0.125f * (Srow[j] - m));
            Srow[j] = e;
            s += e;
        }
        s += __shfl_xor_sync(0xffffffffu, s, 1);
        s += __shfl_xor_sync(0xffffffffu, s, 2);
        const float inv = 1.0f / s;
        __half* Prow = Ph + row * 104;
        for (int j = ja; j < ja + 24; j++) {
            float p = (j >= lo && j <= hi) ? Srow[j] * inv : 0.f;
            Prow[j] = __float2half(p);
        }
    }
    __syncthreads();

    // ---- O = P @ V : warp w -> rows 16*(w&3), cols 32*(w>>2) ----
    {
        const int wr = (w & 3) * 16;
        const int ch = (w >> 2);              // col half
        wmma::fragment<wmma::accumulator, 16, 16, 16, float> of[2];
#pragma unroll
        for (int n = 0; n < 2; n++) wmma::fill_fragment(of[n], 0.0f);
#pragma unroll
        for (int k = 0; k < 6; k++) {
            wmma::fragment<wmma::matrix_a, 16, 16, 16, __half, wmma::row_major> af;
            wmma::load_matrix_sync(af, &Ph[wr * 104 + k * 16], 104);
#pragma unroll
            for (int n = 0; n < 2; n++) {
                wmma::fragment<wmma::matrix_b, 16, 16, 16, __half, wmma::row_major> bf;
                wmma::load_matrix_sync(bf, &Vh[(k * 16) * 72 + (ch * 2 + n) * 16], 72);
                wmma::mma_sync(of[n], af, bf, of[n]);
            }
        }
        float* stg = (float*)(sm + AS_OFF) + w * 320;
        const int lane = tid & 31;
        const int r  = lane >> 1;
        const int c8 = (lane & 1) * 8;
#pragma unroll
        for (int n = 0; n < 2; n++) {
            wmma::store_matrix_sync(stg, of[n], 20, wmma::mem_row_major);
            __syncwarp();
            const float* sp = stg + r * 20 + c8;
            __half2 h0 = __floats2half2_rn(sp[0], sp[1]);
            __half2 h1 = __floats2half2_rn(sp[2], sp[3]);
            __half2 h2 = __floats2half2_rn(sp[4], sp[5]);
            __half2 h3 = __floats2half2_rn(sp[6], sp[7]);
            uint4 u;
            u.x = *reinterpret_cast<uint32_t*>(&h0);
            u.y = *reinterpret_cast<uint32_t*>(&h1);
            u.z = *reinterpret_cast<uint32_t*>(&h2);
            u.w = *reinterpret_cast<uint32_t*>(&h3);
            *(uint4*)(g_attnh + (size_t)(b * KS + s0 + wr + r) * KD
                               + h * 64 + (ch * 2 + n) * 16 + c8) = u;
            __syncwarp();
        }
    }
}

// ---------------------------------------------------------------------------
extern "C" void kernel_launch(void* const* d_in, const int* in_sizes, int n_in,
                              void* d_out, int out_size)
{
    const float* x    = (const float*)d_in[0];
    const float* Wqkv = (const float*)d_in[1];
    const float* bqkv = (const float*)d_in[2];
    const float* Wo   = (const float*)d_in[3];
    const float* bo   = (const float*)d_in[4];
    float* out = (float*)d_out;

    void *p_qkvh, *p_xh, *p_attnh, *p_wqkvh, *p_woh;
    cudaGetSymbolAddress(&p_qkvh,  g_qkvh);
    cudaGetSymbolAddress(&p_xh,    g_xh);
    cudaGetSymbolAddress(&p_attnh, g_attnh);
    cudaGetSymbolAddress(&p_wqkvh, g_wqkvh);
    cudaGetSymbolAddress(&p_woh,   g_woh);

    cudaFuncSetAttribute(gemm_k64<true>,  cudaFuncAttributeMaxDynamicSharedMemorySize, G_SMEM);
    cudaFuncSetAttribute(gemm_k64<false>, cudaFuncAttributeMaxDynamicSharedMemorySize, G_SMEM);
    cudaFuncSetAttribute(attn_wmma, cudaFuncAttributeMaxDynamicSharedMemorySize, ATT_SMEM);

    // 0) fp32 -> fp16 converts
    f2h<<<4096, 256>>>(x,    (__half*)p_xh,    KM * KD);
    f2h<<<1024, 256>>>(Wqkv, (__half*)p_wqkvh, 1024 * 3072);
    f2h<<<512,  256>>>(Wo,   (__half*)p_woh,   1024 * 1024);

    // 1) QKV projection (fp16 out): g_qkvh = x @ Wqkv + bqkv
    gemm_k64<true><<<dim3(3072 / 128, KM / 128), 256, G_SMEM>>>(
        (const __half*)p_xh, (const __half*)p_wqkvh, bqkv, p_qkvh, 3072, 1024);

    // 2) WMMA sliding-window attention -> g_attnh
    attn_wmma<<<dim3(KS / 64, KH, KB), 256, ATT_SMEM>>>();

    // 3) Output projection (fp32 out): out = g_attnh @ Wo + bo
    gemm_k64<false><<<dim3(1024 / 128, KM / 128), 256, G_SMEM>>>(
        (const __half*)p_attnh, (const __half*)p_woh, bo, out, 1024, 1024);
}